// round 16
// baseline (speedup 1.0000x reference)
#include <cuda_runtime.h>
#include <cuda_fp16.h>
#include <cstdint>

#define NB 16
#define NC 64
#define HW 4096      // 64*64
#define HWP 1024     // 32*32
#define CK 8         // C/8
#define CV 32        // C/2

// Scratch (device globals; no allocation allowed)
__device__ float d_theta[NB * CK * HW];          // [b][k][n] fp32
__device__ __half d_phih[NB * HWP * CK];         // [b][m][k] hi
__device__ __half d_phil[NB * HWP * CK];         // [b][m][k] lo
__device__ __half d_gh[NB * CV * HWP];           // [b][c][m] fp16

// ---------------------------------------------------------------------------
__device__ __forceinline__ uint32_t pack2h(float a, float b) {
    __half2 t = __floats2half2_rn(a, b);
    return *(uint32_t*)&t;
}
// split (a,b) -> packed fp16 hi pair, packed fp16 lo (residual) pair
__device__ __forceinline__ void split2h(float a, float b, uint32_t& hi, uint32_t& lo) {
    __half ha = __float2half_rn(a), hb = __float2half_rn(b);
    hi = ((uint32_t)*(unsigned short*)&hb << 16) | (uint32_t)*(unsigned short*)&ha;
    lo = pack2h(a - __half2float(ha), b - __half2float(hb));
}
__device__ __forceinline__ void split1h(float v, __half& h, __half& l) {
    h = __float2half_rn(v);
    l = __float2half_rn(v - __half2float(h));
}
// packed fp16x2 2^x (one MUFU for two exps; output = ready A-fragment)
__device__ __forceinline__ uint32_t ex2h2(uint32_t s) {
    uint32_t r;
    asm("ex2.approx.f16x2 %0, %1;" : "=r"(r) : "r"(s));
    return r;
}

#define MMAH16816(c0,c1,c2,c3,a0,a1,a2,a3,b0,b1) \
    asm volatile("mma.sync.aligned.m16n8k16.row.col.f32.f16.f16.f32 " \
        "{%0,%1,%2,%3}, {%4,%5,%6,%7}, {%8,%9}, {%0,%1,%2,%3};" \
        : "+f"(c0),"+f"(c1),"+f"(c2),"+f"(c3) \
        : "r"(a0),"r"(a1),"r"(a2),"r"(a3),"r"(b0),"r"(b1))

// ---------------------------------------------------------------------------
// Kernel A: 1x1 conv projections + 2x2 maxpool. 2 pixels/thread, 48 channels
// per CTA over a 256-pixel tile (4 image rows). x staged once per pass.
// grid (16, 16). dyn smem 62.5KB, 3 CTAs/SM, single wave.
// ---------------------------------------------------------------------------
#define PJ_W    0
#define PJ_X    (48 * 64 * 4)
#define SMEM_PROJ (PJ_X + 256 * 49 * 4)

__global__ __launch_bounds__(256) void proj_kernel(
    const float* __restrict__ x,
    const float* __restrict__ w_theta,
    const float* __restrict__ w_phi,
    const float* __restrict__ w_g)
{
    extern __shared__ char psm[];
    float* w_s  = (float*)(psm + PJ_W);      // [c][r] transposed
    float* x_s  = (float*)(psm + PJ_X);      // [32][256]
    float* pool = (float*)(psm + PJ_X);      // [256 px][48 ch] stride 49 (overlay)

    const int b = blockIdx.y;
    const int hc = blockIdx.x;
    const int t = threadIdx.x;
    const int pp = t & 127;
    const int h = t >> 7;

    for (int i = t; i < 48 * 64; i += 256) {
        int r = i >> 6, c = i & 63;
        float wv = (r < 8) ? w_theta[r * 64 + c]
                 : (r < 16) ? w_phi[(r - 8) * 64 + c]
                            : w_g[(r - 16) * 64 + c];
        w_s[c * 48 + r] = wv;
    }

    // Rows 4hc..4hc+3 are 256 contiguous floats per channel (W=64).
    const float* xb = x + ((size_t)b * NC) * HW + (size_t)hc * 256;

    float acc0[24], acc1[24];
#pragma unroll
    for (int k = 0; k < 24; k++) { acc0[k] = 0.f; acc1[k] = 0.f; }

#pragma unroll 1
    for (int pass = 0; pass < 2; pass++) {
        const float* xp = xb + (size_t)(pass * 32) * HW;
#pragma unroll 4
        for (int i = t; i < 8192; i += 256)
            x_s[i] = xp[(size_t)(i >> 8) * HW + (i & 255)];
        __syncthreads();
        const int cw0 = pass * 32;
        for (int c = 0; c < 32; c++) {
            float2 xv = *(float2*)&x_s[c * 256 + 2 * pp];
            const float4* wr = (const float4*)&w_s[(cw0 + c) * 48 + h * 24];
            float wv[24];
#pragma unroll
            for (int j = 0; j < 6; j++) {
                float4 wq = wr[j];
                wv[4 * j] = wq.x; wv[4 * j + 1] = wq.y;
                wv[4 * j + 2] = wq.z; wv[4 * j + 3] = wq.w;
            }
#pragma unroll
            for (int k = 0; k < 24; k++) {
                acc0[k] += wv[k] * xv.x;
                acc1[k] += wv[k] * xv.y;
            }
        }
        __syncthreads();   // x_s free for next pass / pooling overlay
    }

    if (h == 0) {
        int p = hc * 256 + 2 * pp;
        float* th = d_theta + (size_t)b * CK * HW;
#pragma unroll
        for (int k = 0; k < 8; k++)
            *(float2*)&th[k * HW + p] = make_float2(acc0[k], acc1[k]);
    }

    // stage all 48 channels for pooling: col = h*24 + k
#pragma unroll
    for (int k = 0; k < 24; k++) {
        pool[(2 * pp) * 49 + h * 24 + k]     = acc0[k];
        pool[(2 * pp + 1) * 49 + h * 24 + k] = acc1[k];
    }
    __syncthreads();

    {
        int mp = t & 63, cg = t >> 6;           // 64 pooled px x 4 channel groups
        int pr = mp >> 5, wc = mp & 31;         // pooled row (0/1), pooled col
        int p00 = pr * 128 + 2 * wc;            // local pixel indices
        int p01 = p00 + 1, p10 = p00 + 64, p11 = p00 + 65;
        int m = (hc * 2 + pr) * 32 + wc;        // global pooled index
#pragma unroll
        for (int j = 0; j < 10; j++) {
            int c48 = 8 + cg * 10 + j;          // pooled channels live in cols 8..47
            float v = fmaxf(fmaxf(pool[p00 * 49 + c48], pool[p01 * 49 + c48]),
                            fmaxf(pool[p10 * 49 + c48], pool[p11 * 49 + c48]));
            if (c48 < 16) {                     // phi channel c48-8
                __half hh, ll;
                split1h(v, hh, ll);
                size_t o = ((size_t)b * HWP + m) * CK + (c48 - 8);
                d_phih[o] = hh; d_phil[o] = ll;
            } else {                            // g channel c48-16 (fp16 single)
                size_t o = ((size_t)b * CV + (c48 - 16)) * HWP + m;
                d_gh[o] = __float2half_rn(v);
            }
        }
    }
}

// ---------------------------------------------------------------------------
// Kernel B: fp16 HMMA flash attention + fused output projection/residual.
// Fragment-pair interleaved smem: phi hi/lo words interleaved (LDS.64 yields
// bh+bl), g key-pairs reordered (LDS.64 yields b0+b1). 6 LDS.64 per chunk
// instead of 12 LDS.32. Online row max, ex2.f16x2 softmax, ones-MMA den,
// split-K x2, fused w_o epilogue. grid (32,16), 512 threads.
// smem: phi 32KB (interleaved) | g 32x2080B (65KB) = 97KB -> 2 CTAs/SM.
// ---------------------------------------------------------------------------
#define PHI   0
#define G_H   32768
#define GSTRB 2080
#define PART  0                      /* overlays phi after main loop */
#define OS    32768                  /* o_s [128][34] floats, overlays g */
#define WS    (32768 + 128 * 34 * 4) /* w_s [32][64] floats */
#define SMEM_ATTN (32768 + 32 * GSTRB)

__global__ __launch_bounds__(512, 2) void attn_mma_kernel(
    const float* __restrict__ x,
    const float* __restrict__ w_o,
    const float* __restrict__ gamma_p,
    float* __restrict__ out)
{
    extern __shared__ char smem[];
    const int tid = threadIdx.x;
    const int lane = tid & 31;
    const int w = tid >> 5;        // 0..15
    const int wq = w & 7;          // query-set id
    const int team = w >> 3;       // 0/1 (key half)
    const int gid = lane >> 2;     // group id 0..7
    const int tig = lane & 3;      // thread in group
    const int b = blockIdx.y;
    const int q0 = blockIdx.x * 128;
    const uint32_t ONES = 0x3C003C00u;      // fp16x2 (1.0, 1.0)
    const float L2E = 1.4426950408889634f;  // log2(e)

    // fill phi interleaved: [m][h0 l0 h1 l1 h2 l2 h3 l3] (32B per key)
    {
        const uint32_t* ph = (const uint32_t*)(d_phih + (size_t)b * HWP * CK);
        const uint32_t* pl = (const uint32_t*)(d_phil + (size_t)b * HWP * CK);
        for (int i = tid; i < 4096; i += 512) {
            int m = i >> 2, j = i & 3;
            *(uint2*)(smem + PHI + m * 32 + j * 8) = make_uint2(ph[i], pl[i]);
        }
    }
    // fill g with key-pair reorder: per row, 16-key block (32B) word order
    // [k0k1][k8k9][k2k3][k10k11][k4k5][k12k13][k6k7][k14k15]
    for (int i = tid; i < 32 * 256; i += 512) {
        int c = i >> 8, r = i & 255;
        int kb = r >> 2, t = r & 3;
        const uint32_t* src = (const uint32_t*)(d_gh + ((size_t)b * CV + c) * HWP);
        uint32_t w0 = src[kb * 8 + t];
        uint32_t w1 = src[kb * 8 + 4 + t];
        *(uint2*)(smem + G_H + c * GSTRB + kb * 32 + t * 8) = make_uint2(w0, w1);
    }

    // theta A fragments (constant across key loop)
    const int qb = q0 + wq * 16;
    const float* th = d_theta + (size_t)b * CK * HW;
    float t00 = th[(2 * tig) * HW + qb + gid];
    float t01 = th[(2 * tig + 1) * HW + qb + gid];
    float t10 = th[(2 * tig) * HW + qb + gid + 8];
    float t11 = th[(2 * tig + 1) * HW + qb + gid + 8];
    uint32_t ah0, al0, ah1, al1;
    split2h(t00, t01, ah0, al0);
    split2h(t10, t11, ah1, al1);
    __syncthreads();

    float o[4][4];
#pragma unroll
    for (int nf = 0; nf < 4; nf++)
#pragma unroll
        for (int j = 0; j < 4; j++) o[nf][j] = 0.f;
    float dn[4] = {0.f, 0.f, 0.f, 0.f};   // den accumulators (ones-MMA)
    float mx0 = -1e30f, mx1 = -1e30f;     // running row maxes
    float nmb0 = 0.f, nmb1 = 0.f;         // -mx * log2(e), updated on rescale

    const uint32_t phi_off = gid * 32 + tig * 8;
    const int m_start = team * 512;

#pragma unroll 2
    for (int m0 = m_start; m0 < m_start + 512; m0 += 16) {
        // ---- GEMM1 for 16 keys; LDS.64 gives (hi,lo) fragment pair ----
        uint2 pA = *(const uint2*)(smem + PHI + m0 * 32 + phi_off);
        uint2 pB = *(const uint2*)(smem + PHI + (m0 + 8) * 32 + phi_off);
        float sA0 = 0.f, sA1 = 0.f, sA2 = 0.f, sA3 = 0.f;
        float sB0 = 0.f, sB1 = 0.f, sB2 = 0.f, sB3 = 0.f;
        MMAH16816(sA0, sA1, sA2, sA3, ah0, ah1, al0, al1, pA.x, pA.x);
        MMAH16816(sA0, sA1, sA2, sA3, ah0, ah1, al0, al1, pA.y, pA.y);
        MMAH16816(sB0, sB1, sB2, sB3, ah0, ah1, al0, al1, pB.x, pB.x);
        MMAH16816(sB0, sB1, sB2, sB3, ah0, ah1, al0, al1, pB.y, pB.y);

        // ---- chunk row max (row gid: sA0,sA1,sB0,sB1; row gid+8: sA2,sA3,sB2,sB3)
        float c0 = fmaxf(fmaxf(sA0, sA1), fmaxf(sB0, sB1));
        float c1 = fmaxf(fmaxf(sA2, sA3), fmaxf(sB2, sB3));
        c0 = fmaxf(c0, __shfl_xor_sync(0xffffffffu, c0, 1));
        c0 = fmaxf(c0, __shfl_xor_sync(0xffffffffu, c0, 2));
        c1 = fmaxf(c1, __shfl_xor_sync(0xffffffffu, c1, 1));
        c1 = fmaxf(c1, __shfl_xor_sync(0xffffffffu, c1, 2));

        // ---- conditional rescale: only when some row's max grew (warp-uniform)
        if (__any_sync(0xffffffffu, (c0 > mx0) | (c1 > mx1))) {
            float nm0 = fmaxf(mx0, c0), nm1 = fmaxf(mx1, c1);
            float sc0 = __expf(mx0 - nm0), sc1 = __expf(mx1 - nm1);
            mx0 = nm0; mx1 = nm1;
            nmb0 = -nm0 * L2E; nmb1 = -nm1 * L2E;
            dn[0] *= sc0; dn[2] *= sc1;
#pragma unroll
            for (int nf = 0; nf < 4; nf++) {
                o[nf][0] *= sc0; o[nf][1] *= sc0;
                o[nf][2] *= sc1; o[nf][3] *= sc1;
            }
        }

        // ---- E = 2^(s*log2e - mx*log2e) via packed fp16x2 ex2 ----
        uint32_t Ah0 = ex2h2(pack2h(fmaf(sA0, L2E, nmb0), fmaf(sA1, L2E, nmb0)));
        uint32_t Ah1 = ex2h2(pack2h(fmaf(sA2, L2E, nmb1), fmaf(sA3, L2E, nmb1)));
        uint32_t Ah2 = ex2h2(pack2h(fmaf(sB0, L2E, nmb0), fmaf(sB1, L2E, nmb0)));
        uint32_t Ah3 = ex2h2(pack2h(fmaf(sB2, L2E, nmb1), fmaf(sB3, L2E, nmb1)));

        // ---- GEMM2: den (ones-B) + 4 channel blocks; LDS.64 gives (b0,b1) ----
        MMAH16816(dn[0], dn[1], dn[2], dn[3], Ah0, Ah1, Ah2, Ah3, ONES, ONES);
        const uint32_t mo = (uint32_t)(m0 * 2) + tig * 8 + gid * GSTRB;
#pragma unroll
        for (int nf = 0; nf < 4; nf++) {
            uint2 gw = *(const uint2*)(smem + G_H + nf * 8 * GSTRB + mo);
            MMAH16816(o[nf][0], o[nf][1], o[nf][2], o[nf][3],
                      Ah0, Ah1, Ah2, Ah3, gw.x, gw.y);
        }
    }

    __syncthreads();   // phi + g planes dead; overlays become live

    // stage w_o transposed: w_s[c][ch] = w_o[ch][c]
    {
        float* w_s = (float*)(smem + WS);
        for (int i = tid; i < 2048; i += 512) {
            int ch = i >> 5, c = i & 31;
            w_s[c * 64 + ch] = w_o[i];
        }
    }

    // ---- split-K combine with max reconciliation ----
    if (team == 1) {
        float* pp = (float*)(smem + PART) + ((w - 8) * 32 + lane) * 20;
#pragma unroll
        for (int nf = 0; nf < 4; nf++)
#pragma unroll
            for (int j = 0; j < 4; j++) pp[nf * 4 + j] = o[nf][j];
        pp[16] = dn[0]; pp[17] = dn[2];
        pp[18] = mx0;   pp[19] = mx1;
    }
    __syncthreads();
    if (team == 0) {
        const float* pp = (const float*)(smem + PART) + (w * 32 + lane) * 20;
        float om0 = pp[18], om1 = pp[19];
        float gm0 = fmaxf(mx0, om0), gm1 = fmaxf(mx1, om1);
        float a0 = __expf(mx0 - gm0), b0s = __expf(om0 - gm0);
        float a1 = __expf(mx1 - gm1), b1s = __expf(om1 - gm1);
#pragma unroll
        for (int nf = 0; nf < 4; nf++) {
            o[nf][0] = o[nf][0] * a0 + pp[nf * 4 + 0] * b0s;
            o[nf][1] = o[nf][1] * a0 + pp[nf * 4 + 1] * b0s;
            o[nf][2] = o[nf][2] * a1 + pp[nf * 4 + 2] * b1s;
            o[nf][3] = o[nf][3] * a1 + pp[nf * 4 + 3] * b1s;
        }
        float den0 = dn[0] * a0 + pp[16] * b0s;
        float den1 = dn[2] * a1 + pp[17] * b1s;
        float i0 = 1.f / den0, i1 = 1.f / den1;

        // write normalized o to smem [q_local][c], stride 34 (float2-aligned)
        float* os = (float*)(smem + OS);
        int ql = wq * 16 + gid;
#pragma unroll
        for (int nf = 0; nf < 4; nf++) {
            int c = nf * 8 + 2 * tig;
            *(float2*)&os[ql * 34 + c]       = make_float2(o[nf][0] * i0, o[nf][1] * i0);
            *(float2*)&os[(ql + 8) * 34 + c] = make_float2(o[nf][2] * i1, o[nf][3] * i1);
        }
    }
    __syncthreads();

    // ---- fused output projection: out = gamma * (w_o @ o) + x ----
    {
        const float* os = (const float*)(smem + OS);
        const float* w_s = (const float*)(smem + WS);
        const float gamma = *gamma_p;
        int q = tid & 127, cg = tid >> 7;       // 128 queries x 4 ch-groups of 16
        float accf[16];
#pragma unroll
        for (int j = 0; j < 16; j++) accf[j] = 0.f;
        for (int c = 0; c < 32; c++) {
            float ov = os[q * 34 + c];
            const float4* wr = (const float4*)&w_s[c * 64 + cg * 16];
#pragma unroll
            for (int j4 = 0; j4 < 4; j4++) {
                float4 wq4 = wr[j4];
                accf[4 * j4]     += wq4.x * ov;
                accf[4 * j4 + 1] += wq4.y * ov;
                accf[4 * j4 + 2] += wq4.z * ov;
                accf[4 * j4 + 3] += wq4.w * ov;
            }
        }
        int p = q0 + q;
        const float* xb = x + (size_t)b * NC * HW + p;
        float* ob = out + (size_t)b * NC * HW + p;
#pragma unroll
        for (int j = 0; j < 16; j++) {
            int ch = cg * 16 + j;
            ob[(size_t)ch * HW] = gamma * accf[j] + xb[(size_t)ch * HW];
        }
    }
}

// ---------------------------------------------------------------------------
extern "C" void kernel_launch(void* const* d_in, const int* in_sizes, int n_in,
                              void* d_out, int out_size)
{
    const float* x       = (const float*)d_in[0];
    const float* w_theta = (const float*)d_in[1];
    const float* w_phi   = (const float*)d_in[2];
    const float* w_g     = (const float*)d_in[3];
    const float* w_o     = (const float*)d_in[4];
    const float* gamma_p = (const float*)d_in[5];
    float* out = (float*)d_out;

    cudaFuncSetAttribute(proj_kernel, cudaFuncAttributeMaxDynamicSharedMemorySize,
                         SMEM_PROJ);
    proj_kernel<<<dim3(16, 16), 256, SMEM_PROJ>>>(x, w_theta, w_phi, w_g);

    cudaFuncSetAttribute(attn_mma_kernel, cudaFuncAttributeMaxDynamicSharedMemorySize,
                         SMEM_ATTN);
    attn_mma_kernel<<<dim3(32, 16), 512, SMEM_ATTN>>>(x, w_o, gamma_p, out);
}